// round 9
// baseline (speedup 1.0000x reference)
#include <cuda_runtime.h>

#define BB 64      // batch
#define NN 1024    // nodes
#define EE 16384   // edges
#define DD 1024    // input dim
#define CC 128     // channels
#define KMAXC 128  // indeg class cap
#define NKPAD 64   // padded class count (actual ~35)
#define ADJS 96    // adjacency stride (max indeg ~40)
#define MAXF2 512  // cap |F2| (actual ~225)
#define MAXF3 64   // cap |F3| (actual ~16)
#define NKC 16     // k-chunks for the embedding GEMM
#define RELU(x) fmaxf((x), 0.f)

// ---------------- device scratch ----------------
__device__ int   g_e32;
__device__ int   g_indeg[NN];
__device__ int   g_adj[NN * ADJS];
__device__ int   g_inF3[NN], g_inF2[NN];
__device__ int   g_F3[MAXF3], g_F2[MAXF2];
__device__ int   g_slotF2[NN], g_slotF3[NN];
__device__ int   g_slot2cls[NKPAD];
__device__ int   g_cls2slotG[KMAXC];
__device__ int   g_nF3, g_nF2, g_nk;
__device__ float g_cnt2[MAXF2 * NKPAD];       // batch-invariant class-count matrix
__device__ float g_Epart[NKC * BB * CC];      // embedding partial sums (k-split)
__device__ float g_h2[BB * MAXF2 * CC];       // per-graph h2

// ---------------- preprocessing ----------------
__global__ void k_init(const void* ei) {
    int t = blockIdx.x * blockDim.x + threadIdx.x;
    int nth = gridDim.x * blockDim.x;
    for (int i = t; i < NN; i += nth) { g_indeg[i] = 0; g_inF3[i] = 0; g_inF2[i] = 0; }
    for (int i = t; i < MAXF2 * NKPAD; i += nth) g_cnt2[i] = 0.f;
    if (t == 0) {
        g_nF3 = 0; g_nF2 = 0;
        // dtype detect: int32 data reinterpreted as int64 gives out-of-range values
        const long long* p = (const long long*)ei;
        int e32 = 0;
        for (int j = 0; j < 16; j++) { long long v = p[j]; if (v < 0 || v >= (long long)NN) e32 = 1; }
        g_e32 = e32;
    }
}

__global__ void k_edges(const void* ei) {
    int t = blockIdx.x * blockDim.x + threadIdx.x;
    int nth = gridDim.x * blockDim.x;
    int e32 = g_e32;
    const int* pi = (const int*)ei;
    const long long* pl = (const long long*)ei;
    for (int e = t; e < EE; e += nth) {
        int sv = e32 ? pi[e] : (int)pl[e];
        int dv = e32 ? pi[EE + e] : (int)pl[EE + e];
        int pos = atomicAdd(&g_indeg[dv], 1);
        if (pos < ADJS) g_adj[dv * ADJS + pos] = sv;
        if (dv == 0) {
            if (atomicExch(&g_inF3[sv], 1) == 0) {
                int sl = atomicAdd(&g_nF3, 1);
                if (sl < MAXF3) { g_F3[sl] = sv; g_slotF3[sv] = sl; }
                else g_slotF3[sv] = MAXF3 - 1;
            }
        }
    }
}

// block 0: class compaction; blocks 1..24: F2 discovery (parallel over F3 x ADJS)
__global__ void __launch_bounds__(256) k_f2() {
    if (blockIdx.x == 0) {
        __shared__ int s_used[KMAXC];
        int t = threadIdx.x;
        if (t < KMAXC) s_used[t] = 0;
        __syncthreads();
        for (int v = t; v < NN; v += 256)
            s_used[min(g_indeg[v], KMAXC - 1)] = 1;
        __syncthreads();
        if (t == 0) {   // deterministic compaction
            int nk = 0;
            for (int k = 0; k < KMAXC; k++) if (s_used[k]) {
                g_cls2slotG[k] = (nk < NKPAD) ? nk : NKPAD - 1;
                if (nk < NKPAD) g_slot2cls[nk] = k;
                nk++;
            } else {
                g_cls2slotG[k] = 0;
            }
            g_nk = min(nk, NKPAD);
        }
        return;
    }
    int idx = (blockIdx.x - 1) * 256 + threadIdx.x;   // over MAXF3 * ADJS
    int f = idx / ADJS, j = idx % ADJS;
    int nf3 = min(g_nF3, MAXF3);
    if (f >= nf3) return;
    int w = g_F3[f];
    if (j >= min(g_indeg[w], ADJS)) return;
    int src = g_adj[w * ADJS + j];
    if (atomicExch(&g_inF2[src], 1) == 0) {
        int sl = atomicAdd(&g_nF2, 1);
        if (sl < MAXF2) { g_F2[sl] = src; g_slotF2[src] = sl; }
        else g_slotF2[src] = MAXF2 - 1;
    }
}

// one thread per (F2 slot, adjacency position): fire-and-forget atomic counts
__global__ void __launch_bounds__(256) k_cnt2() {
    int idx = blockIdx.x * 256 + threadIdx.x;         // over MAXF2 * ADJS
    int sl = idx / ADJS, j = idx % ADJS;
    int nf2 = min(g_nF2, MAXF2);
    if (sl >= nf2) return;
    int u = g_F2[sl];
    if (j >= min(g_indeg[u], ADJS)) return;
    int src = g_adj[u * ADJS + j];
    int cs = g_cls2slotG[min(g_indeg[src], KMAXC - 1)];
    atomicAdd(&g_cnt2[sl * NKPAD + cs], 1.f);
}

// ---------------- embedding partials: grid (4 strips, 16 kchunks), W_emb read ONCE ----------------
__global__ void __launch_bounds__(256) k_embedA(const float* __restrict__ x,
                                                const float* __restrict__ W_emb) {
    __shared__ float xs[BB * 64];   // x[0..63][k0..k0+63]
    int strip = blockIdx.x, kc = blockIdx.y;
    int t = threadIdx.x;
    int k0 = kc * 64;
    for (int i = t; i < BB * 16; i += 256) {   // 1024 float4
        int b = i >> 4, j4 = (i & 15) * 4;
        *(float4*)&xs[b * 64 + j4] = *(const float4*)&x[b * DD + k0 + j4];
    }
    __syncthreads();
    int col = strip * 32 + (t & 31);
    int b0 = (t >> 5) * 8;
    float acc[8] = {};
    for (int k = 0; k < 64; k += 4) {
        float w0 = W_emb[(k0 + k + 0) * CC + col];
        float w1 = W_emb[(k0 + k + 1) * CC + col];
        float w2 = W_emb[(k0 + k + 2) * CC + col];
        float w3 = W_emb[(k0 + k + 3) * CC + col];
#pragma unroll
        for (int r = 0; r < 8; r++) {
            float4 a = *(float4*)&xs[(b0 + r) * 64 + k];
            acc[r] += a.x * w0 + a.y * w1 + a.z * w2 + a.w * w3;
        }
    }
#pragma unroll
    for (int r = 0; r < 8; r++)
        g_Epart[(kc * BB + b0 + r) * CC + col] = acc[r];
}

// ---------------- mid: e-reduce -> hw0 -> A1 -> hw1c(half) -> h2(half), grid (64, 2) ----------------
// smem floats: sWh 8192 | sA1 8192 | sH1 4096 | sCnt 4096 | e_s 128 | hw0f 128 | part 256 | bcs 128
#define SMEM_MID ((8192 + 8192 + 4096 + 4096 + 128 + 128 + 256 + 128) * 4)
__global__ void __launch_bounds__(256, 1) k_mid(const float* __restrict__ W_conv,
                                                const float* __restrict__ b_conv,
                                                const float* __restrict__ b_emb) {
    extern __shared__ float S[];
    float* sWh  = S;           // [128][64]  W_conv columns n0..n0+63
    float* sA1  = S + 8192;    // [64][128]
    float* sH1  = S + 16384;   // [64][64]   hw1c half
    float* sCnt = S + 20480;   // [64][64]
    float* e_s  = S + 24576;
    float* hw0f = S + 24704;
    float* part = S + 24832;
    float* bcs  = S + 25088;
    __shared__ int scls[NKPAD];

    int b = blockIdx.x, n0 = blockIdx.y * 64;
    int t = threadIdx.x, warp = t >> 5, lane = t & 31;
    int nk = g_nk, nF2 = min(g_nF2, MAXF2);
    int nk4 = (nk + 3) & ~3;

    if (t < CC) {   // e = relu(sum of 16 k-partials + b_emb)
        float s = b_emb[t];
#pragma unroll
        for (int kc = 0; kc < NKC; kc++) s += g_Epart[(kc * BB + b) * CC + t];
        e_s[t] = RELU(s);
        bcs[t] = b_conv[t];
    }
    if (t < NKPAD) scls[t] = g_slot2cls[t];
#pragma unroll
    for (int q = 0; q < 8; q++) {          // W half: 128x64 = 2048 float4
        int idx = t + q * 256;
        int row = idx >> 4, c4 = (idx & 15) * 4;
        *(float4*)&sWh[row * 64 + c4] = *(const float4*)&W_conv[row * CC + n0 + c4];
    }
    __syncthreads();

    // hw0 full (redundant per half), K split over 2 thread groups
    {
        int c = t & 127, kh = t >> 7;
        float a = 0.f;
#pragma unroll 8
        for (int j = kh * 64; j < kh * 64 + 64; j++)
            a += e_s[j] * W_conv[j * CC + c];
        part[t] = a;
    }
    __syncthreads();
    if (t < CC) hw0f[t] = part[t] + part[t + 128];
    __syncthreads();

    // A1[slot][k] = relu(cls*hw0[k] + b) (rows >= nk zero)
    for (int idx = t; idx < NKPAD * CC; idx += 256) {
        int slot = idx >> 7, k = idx & 127;
        float v = 0.f;
        if (slot < nk) v = RELU((float)scls[slot] * hw0f[k] + bcs[k]);
        sA1[idx] = v;
    }
    __syncthreads();

    // hw1c half: rows 0..ceil8(nk), [rows x 64] = sA1 @ sWh, K=128
    {
        int rb = warp * 8, cb = lane * 2;
        if (rb < nk) {
            float acc[8][2] = {};
            for (int k = 0; k < CC; k += 4) {
                float2 wv0 = *(float2*)&sWh[(k + 0) * 64 + cb];
                float2 wv1 = *(float2*)&sWh[(k + 1) * 64 + cb];
                float2 wv2 = *(float2*)&sWh[(k + 2) * 64 + cb];
                float2 wv3 = *(float2*)&sWh[(k + 3) * 64 + cb];
#pragma unroll
                for (int r = 0; r < 8; r++) {
                    float4 a = *(float4*)&sA1[(rb + r) * CC + k];
                    acc[r][0] += a.x * wv0.x + a.y * wv1.x + a.z * wv2.x + a.w * wv3.x;
                    acc[r][1] += a.x * wv0.y + a.y * wv1.y + a.z * wv2.y + a.w * wv3.y;
                }
            }
#pragma unroll
            for (int r = 0; r < 8; r++)
                *(float2*)&sH1[(rb + r) * 64 + cb] = make_float2(acc[r][0], acc[r][1]);
        }
    }
    __syncthreads();

    // h2 half: relu(Cnt @ hw1c_half + b), K bounded by nk4, chunks of 64 rows
    {
        int rb = warp * 8, cb = lane * 2;
        float2 bc2 = *(float2*)&bcs[n0 + cb];
        for (int r0 = 0; r0 < nF2; r0 += 64) {
#pragma unroll
            for (int q = 0; q < 4; q++)
                ((float4*)sCnt)[t + q * 256] = ((const float4*)&g_cnt2[r0 * NKPAD])[t + q * 256];
            __syncthreads();
            float acc[8][2] = {};
            for (int k = 0; k < nk4; k += 4) {
                float2 wv0 = *(float2*)&sH1[(k + 0) * 64 + cb];
                float2 wv1 = *(float2*)&sH1[(k + 1) * 64 + cb];
                float2 wv2 = *(float2*)&sH1[(k + 2) * 64 + cb];
                float2 wv3 = *(float2*)&sH1[(k + 3) * 64 + cb];
#pragma unroll
                for (int r = 0; r < 8; r++) {
                    float4 a = *(float4*)&sCnt[(rb + r) * NKPAD + k];
                    acc[r][0] += a.x * wv0.x + a.y * wv1.x + a.z * wv2.x + a.w * wv3.x;
                    acc[r][1] += a.x * wv0.y + a.y * wv1.y + a.z * wv2.y + a.w * wv3.y;
                }
            }
#pragma unroll
            for (int r = 0; r < 8; r++) {
                int row = r0 + rb + r;
                if (row < nF2)
                    *(float2*)&g_h2[(((unsigned)b << 9) + row) * CC + n0 + cb] =
                        make_float2(RELU(acc[r][0] + bc2.x), RELU(acc[r][1] + bc2.y));
            }
            __syncthreads();
        }
    }
}

// ---------------- tail: h3 at F3, conv4 at node0, classifier; grid (64) ----------------
// smem floats: sW 16384 | h3s 8192 | rowbuf 1024 | agg 128 | red 8 | bcs 128
#define SMEM_TAIL ((16384 + 8192 + 1024 + 128 + 8 + 128) * 4)
__global__ void __launch_bounds__(256, 1) k_tail(const float* __restrict__ W_conv,
                                                 const float* __restrict__ b_conv,
                                                 const float* __restrict__ Wcls,
                                                 const float* __restrict__ bcls,
                                                 float* __restrict__ out) {
    extern __shared__ float S[];
    float* sW     = S;
    float* h3s    = S + 16384;   // [64][128]
    float* rowbuf = S + 24576;   // [8][128]
    float* agg    = S + 25600;
    float* red    = S + 25728;
    float* bcs    = S + 25736;
    int b = blockIdx.x, t = threadIdx.x, warp = t >> 5, lane = t & 31;
    int nF3 = min(g_nF3, MAXF3);
#pragma unroll
    for (int q = 0; q < 16; q++)
        ((float4*)sW)[t + q * 256] = ((const float4*)W_conv)[t + q * 256];
    if (t < CC) bcs[t] = b_conv[t];
    __syncthreads();

    for (int f = warp; f < nF3; f += 8) {
        int node = g_F3[f];
        int deg = min(g_indeg[node], ADJS);
        float a0 = 0.f, a1 = 0.f, a2 = 0.f, a3 = 0.f;
        for (int j = 0; j < deg; j++) {
            int src = g_adj[node * ADJS + j];
            const float* p = &g_h2[(((unsigned)b << 9) + g_slotF2[src]) * CC];
            a0 += p[lane]; a1 += p[lane + 32]; a2 += p[lane + 64]; a3 += p[lane + 96];
        }
        float* rb = &rowbuf[warp * CC];
        rb[lane] = a0; rb[lane + 32] = a1; rb[lane + 64] = a2; rb[lane + 96] = a3;
        __syncwarp();
        float y0 = 0.f, y1 = 0.f, y2 = 0.f, y3 = 0.f;
#pragma unroll 4
        for (int j = 0; j < CC; j++) {
            float r = rb[j];
            const float* wr = &sW[j * CC];
            y0 += r * wr[lane]; y1 += r * wr[lane + 32];
            y2 += r * wr[lane + 64]; y3 += r * wr[lane + 96];
        }
        h3s[f * CC + lane]      = RELU(y0 + bcs[lane]);
        h3s[f * CC + lane + 32] = RELU(y1 + bcs[lane + 32]);
        h3s[f * CC + lane + 64] = RELU(y2 + bcs[lane + 64]);
        h3s[f * CC + lane + 96] = RELU(y3 + bcs[lane + 96]);
        __syncwarp();
    }
    __syncthreads();

    if (t < CC) {
        int deg0 = min(g_indeg[0], ADJS);
        float a = 0.f;
        for (int j = 0; j < deg0; j++)
            a += h3s[g_slotF3[g_adj[j]] * CC + t];
        agg[t] = a;
    }
    __syncthreads();
    if (t < CC) {
        float y = 0.f;
#pragma unroll 8
        for (int j = 0; j < CC; j++) y += agg[j] * sW[j * CC + t];
        y = RELU(y + bcs[t]);
        float v = y * Wcls[t];
#pragma unroll
        for (int o = 16; o; o >>= 1) v += __shfl_xor_sync(0xffffffffu, v, o);
        if (lane == 0) red[warp] = v;
    }
    __syncthreads();
    if (t == 0) out[b] = red[0] + red[1] + red[2] + red[3] + bcls[0];
}

// ---------------- launch ----------------
extern "C" void kernel_launch(void* const* d_in, const int* in_sizes, int n_in,
                              void* d_out, int out_size) {
    const float* x      = (const float*)d_in[0];
    const void*  ei     = d_in[1];
    const float* W_emb  = (const float*)d_in[2];
    const float* b_emb  = (const float*)d_in[3];
    const float* W_conv = (const float*)d_in[4];
    const float* b_conv = (const float*)d_in[5];
    const float* W_cls  = (const float*)d_in[6];
    const float* b_cls  = (const float*)d_in[7];
    float* out = (float*)d_out;

    (void)cudaFuncSetAttribute(k_mid,  cudaFuncAttributeMaxDynamicSharedMemorySize, SMEM_MID);
    (void)cudaFuncSetAttribute(k_tail, cudaFuncAttributeMaxDynamicSharedMemorySize, SMEM_TAIL);

    k_init<<<16, 256>>>(ei);
    k_edges<<<16, 256>>>(ei);
    k_embedA<<<dim3(4, NKC), 256>>>(x, W_emb);
    k_f2<<<1 + (MAXF3 * ADJS + 255) / 256, 256>>>();
    k_cnt2<<<(MAXF2 * ADJS + 255) / 256, 256>>>();
    k_mid<<<dim3(BB, 2), 256, SMEM_MID>>>(W_conv, b_conv, b_emb);
    k_tail<<<BB, 256, SMEM_TAIL>>>(W_conv, b_conv, W_cls, b_cls, out);
}

// round 10
// speedup vs baseline: 1.5510x; 1.5510x over previous
#include <cuda_runtime.h>

#define NB 128     // persistent grid size (<= 148 SMs, 1 block/SM)
#define BB 64      // batch
#define NN 1024    // nodes
#define EE 16384   // edges
#define DD 1024    // input dim
#define CC 128     // channels
#define KMAXC 128  // indeg class cap
#define NKPAD 64   // padded class count (actual ~35)
#define ADJS 96    // adjacency stride (max indeg ~40)
#define MAXF2 512  // cap |F2| (actual ~225)
#define MAXF3 64   // cap |F3| (actual ~16)
#define NKC 16     // k-chunks for embedding GEMM
#define RELU(x) fmaxf((x), 0.f)

// ---------------- device scratch ----------------
__device__ int   g_e32;
__device__ int   g_indeg[NN];
__device__ int   g_adj[NN * ADJS];
__device__ int   g_inF3[NN], g_inF2[NN];
__device__ int   g_F3[MAXF3], g_F2[MAXF2];
__device__ int   g_slotF2[NN], g_slotF3[NN];
__device__ int   g_slot2cls[NKPAD];
__device__ int   g_cls2slotG[KMAXC];
__device__ int   g_nF3, g_nF2, g_nk;
__device__ float g_cnt2[MAXF2 * NKPAD];
__device__ float g_Epart[NKC * BB * CC];
__device__ float g_h2[BB * MAXF2 * CC];
__device__ unsigned g_arrive;   // zero-initialized; returns to 0 after each barrier
__device__ unsigned g_gen;      // monotonically increasing generation

// ---------------- software grid barrier (all NB blocks co-resident) ----------------
__device__ __forceinline__ void gridbar() {
    __syncthreads();
    __threadfence();                       // make this thread's writes visible
    if (threadIdx.x == 0) {
        unsigned gen = atomicAdd(&g_gen, 0u);
        if (atomicAdd(&g_arrive, 1u) == NB - 1) {
            g_arrive = 0u;
            __threadfence();
            atomicAdd(&g_gen, 1u);
        } else {
            while (atomicAdd(&g_gen, 0u) == gen) { }
        }
    }
    __syncthreads();
}

// smem (floats): max(mid 25216, tail 25864, embed 4096) = 25864
#define SMEM_ALL (25864 * 4)

__global__ void __launch_bounds__(256, 1)
k_all(const float* __restrict__ x, const void* __restrict__ ei,
      const float* __restrict__ W_emb, const float* __restrict__ b_emb,
      const float* __restrict__ W_conv, const float* __restrict__ b_conv,
      const float* __restrict__ Wcls, const float* __restrict__ bcls,
      float* __restrict__ out) {
    extern __shared__ float S[];
    __shared__ int s_used[KMAXC];
    __shared__ int scls[NKPAD];
    const int blk = blockIdx.x, t = threadIdx.x;
    const int warp = t >> 5, lane = t & 31;

    // ================= phase 0: zero + dtype detect =================
    {
        int gt = blk * 256 + t, nth = NB * 256;
        for (int i = gt; i < NN; i += nth) { g_indeg[i] = 0; g_inF3[i] = 0; g_inF2[i] = 0; }
        for (int i = gt; i < MAXF2 * NKPAD; i += nth) g_cnt2[i] = 0.f;
        if (gt == 0) {
            g_nF3 = 0; g_nF2 = 0;
            const long long* p = (const long long*)ei;
            int e32 = 0;
            for (int j = 0; j < 16; j++) { long long v = p[j]; if (v < 0 || v >= (long long)NN) e32 = 1; }
            g_e32 = e32;
        }
    }
    gridbar();

    // ================= phase 1: edges (blocks 0-31) | embed partials (blocks 32-95) =================
    if (blk < 32) {
        int e32 = g_e32;
        const int* pi = (const int*)ei;
        const long long* pl = (const long long*)ei;
        for (int e = blk * 256 + t; e < EE; e += 32 * 256) {
            int sv = e32 ? pi[e] : (int)pl[e];
            int dv = e32 ? pi[EE + e] : (int)pl[EE + e];
            int pos = atomicAdd(&g_indeg[dv], 1);
            if (pos < ADJS) g_adj[dv * ADJS + pos] = sv;
            if (dv == 0) {
                if (atomicExch(&g_inF3[sv], 1) == 0) {
                    int sl = atomicAdd(&g_nF3, 1);
                    if (sl < MAXF3) { g_F3[sl] = sv; g_slotF3[sv] = sl; }
                    else g_slotF3[sv] = MAXF3 - 1;
                }
            }
        }
    } else if (blk < 96) {
        // embedding partials: unit -> (strip, kc); W_emb read once chip-wide
        float* xs = S;                       // [64][64]
        int unit = blk - 32;
        int strip = unit >> 4, kc = unit & 15;
        int k0 = kc * 64;
        for (int i = t; i < BB * 16; i += 256) {
            int b = i >> 4, j4 = (i & 15) * 4;
            *(float4*)&xs[b * 64 + j4] = *(const float4*)&x[b * DD + k0 + j4];
        }
        __syncthreads();
        int col = strip * 32 + lane;
        int b0 = warp * 8;
        float acc[8] = {};
        for (int k = 0; k < 64; k += 4) {
            float w0 = W_emb[(k0 + k + 0) * CC + col];
            float w1 = W_emb[(k0 + k + 1) * CC + col];
            float w2 = W_emb[(k0 + k + 2) * CC + col];
            float w3 = W_emb[(k0 + k + 3) * CC + col];
#pragma unroll
            for (int r = 0; r < 8; r++) {
                float4 a = *(float4*)&xs[(b0 + r) * 64 + k];
                acc[r] += a.x * w0 + a.y * w1 + a.z * w2 + a.w * w3;
            }
        }
#pragma unroll
        for (int r = 0; r < 8; r++)
            g_Epart[(kc * BB + b0 + r) * CC + col] = acc[r];
    }
    gridbar();

    // ================= phase 2: classes (block 0) | F2 discovery (blocks 1-24) =================
    if (blk == 0) {
        if (t < KMAXC) s_used[t] = 0;
        __syncthreads();
        for (int v = t; v < NN; v += 256)
            s_used[min(g_indeg[v], KMAXC - 1)] = 1;
        __syncthreads();
        if (t == 0) {
            int nk = 0;
            for (int k = 0; k < KMAXC; k++) {
                if (s_used[k]) {
                    g_cls2slotG[k] = (nk < NKPAD) ? nk : NKPAD - 1;
                    if (nk < NKPAD) g_slot2cls[nk] = k;
                    nk++;
                } else g_cls2slotG[k] = 0;
            }
            g_nk = min(nk, NKPAD);
        }
    } else if (blk <= 24) {
        int idx = (blk - 1) * 256 + t;       // over MAXF3 * ADJS = 6144
        int f = idx / ADJS, j = idx % ADJS;
        int nf3 = min(g_nF3, MAXF3);
        if (f < nf3) {
            int w = g_F3[f];
            if (j < min(g_indeg[w], ADJS)) {
                int src = g_adj[w * ADJS + j];
                if (atomicExch(&g_inF2[src], 1) == 0) {
                    int sl = atomicAdd(&g_nF2, 1);
                    if (sl < MAXF2) { g_F2[sl] = src; g_slotF2[src] = sl; }
                    else g_slotF2[src] = MAXF2 - 1;
                }
            }
        }
    }
    gridbar();

    // ================= phase 3: class-count matrix =================
    {
        int nf2 = min(g_nF2, MAXF2);
        for (int idx = blk * 256 + t; idx < MAXF2 * ADJS; idx += NB * 256) {
            int sl = idx / ADJS, j = idx % ADJS;
            if (sl < nf2) {
                int u = g_F2[sl];
                if (j < min(g_indeg[u], ADJS)) {
                    int src = g_adj[u * ADJS + j];
                    int cs = g_cls2slotG[min(g_indeg[src], KMAXC - 1)];
                    atomicAdd(&g_cnt2[sl * NKPAD + cs], 1.f);
                }
            }
        }
    }
    gridbar();

    // ================= phase 4: mid (b = blk>>1, col-half = blk&1) =================
    {
        float* sWh  = S;           // [128][64]
        float* sA1  = S + 8192;    // [64][128]
        float* sH1  = S + 16384;   // [64][64]
        float* sCnt = S + 20480;   // [64][64]
        float* e_s  = S + 24576;
        float* hw0f = S + 24704;
        float* part = S + 24832;
        float* bcs  = S + 25088;
        int b = blk >> 1, n0 = (blk & 1) * 64;
        int nk = g_nk, nF2 = min(g_nF2, MAXF2);
        int nk4 = (nk + 3) & ~3;

        if (t < CC) {
            float s = b_emb[t];
#pragma unroll
            for (int kc = 0; kc < NKC; kc++) s += g_Epart[(kc * BB + b) * CC + t];
            e_s[t] = RELU(s);
            bcs[t] = b_conv[t];
        }
        if (t < NKPAD) scls[t] = g_slot2cls[t];
#pragma unroll
        for (int q = 0; q < 8; q++) {
            int idx = t + q * 256;
            int row = idx >> 4, c4 = (idx & 15) * 4;
            *(float4*)&sWh[row * 64 + c4] = *(const float4*)&W_conv[row * CC + n0 + c4];
        }
        __syncthreads();

        {   // hw0 full, K split over 2 groups
            int c = t & 127, kh = t >> 7;
            float a = 0.f;
#pragma unroll 8
            for (int j = kh * 64; j < kh * 64 + 64; j++)
                a += e_s[j] * W_conv[j * CC + c];
            part[t] = a;
        }
        __syncthreads();
        if (t < CC) hw0f[t] = part[t] + part[t + 128];
        __syncthreads();

        for (int idx = t; idx < NKPAD * CC; idx += 256) {
            int slot = idx >> 7, k = idx & 127;
            float v = 0.f;
            if (slot < nk) v = RELU((float)scls[slot] * hw0f[k] + bcs[k]);
            sA1[idx] = v;
        }
        __syncthreads();

        {   // hw1c half
            int rb = warp * 8, cb = lane * 2;
            if (rb < nk) {
                float acc[8][2] = {};
                for (int k = 0; k < CC; k += 4) {
                    float2 wv0 = *(float2*)&sWh[(k + 0) * 64 + cb];
                    float2 wv1 = *(float2*)&sWh[(k + 1) * 64 + cb];
                    float2 wv2 = *(float2*)&sWh[(k + 2) * 64 + cb];
                    float2 wv3 = *(float2*)&sWh[(k + 3) * 64 + cb];
#pragma unroll
                    for (int r = 0; r < 8; r++) {
                        float4 a = *(float4*)&sA1[(rb + r) * CC + k];
                        acc[r][0] += a.x * wv0.x + a.y * wv1.x + a.z * wv2.x + a.w * wv3.x;
                        acc[r][1] += a.x * wv0.y + a.y * wv1.y + a.z * wv2.y + a.w * wv3.y;
                    }
                }
#pragma unroll
                for (int r = 0; r < 8; r++)
                    *(float2*)&sH1[(rb + r) * 64 + cb] = make_float2(acc[r][0], acc[r][1]);
            }
        }
        __syncthreads();

        {   // h2 half
            int rb = warp * 8, cb = lane * 2;
            float2 bc2 = *(float2*)&bcs[n0 + cb];
            for (int r0 = 0; r0 < nF2; r0 += 64) {
#pragma unroll
                for (int q = 0; q < 4; q++)
                    ((float4*)sCnt)[t + q * 256] = ((const float4*)&g_cnt2[r0 * NKPAD])[t + q * 256];
                __syncthreads();
                float acc[8][2] = {};
                for (int k = 0; k < nk4; k += 4) {
                    float2 wv0 = *(float2*)&sH1[(k + 0) * 64 + cb];
                    float2 wv1 = *(float2*)&sH1[(k + 1) * 64 + cb];
                    float2 wv2 = *(float2*)&sH1[(k + 2) * 64 + cb];
                    float2 wv3 = *(float2*)&sH1[(k + 3) * 64 + cb];
#pragma unroll
                    for (int r = 0; r < 8; r++) {
                        float4 a = *(float4*)&sCnt[(rb + r) * NKPAD + k];
                        acc[r][0] += a.x * wv0.x + a.y * wv1.x + a.z * wv2.x + a.w * wv3.x;
                        acc[r][1] += a.x * wv0.y + a.y * wv1.y + a.z * wv2.y + a.w * wv3.y;
                    }
                }
#pragma unroll
                for (int r = 0; r < 8; r++) {
                    int row = r0 + rb + r;
                    if (row < nF2)
                        *(float2*)&g_h2[(((unsigned)b << 9) + row) * CC + n0 + cb] =
                            make_float2(RELU(acc[r][0] + bc2.x), RELU(acc[r][1] + bc2.y));
                }
                __syncthreads();
            }
        }
    }
    gridbar();

    // ================= phase 5: tail (blocks 0-63) =================
    if (blk < BB) {
        float* sW     = S;            // [128][128]
        float* h3s    = S + 16384;    // [64][128]
        float* rowbuf = S + 24576;    // [8][128]
        float* agg    = S + 25600;
        float* red    = S + 25728;
        float* bcs    = S + 25736;
        int b = blk;
        int nF3 = min(g_nF3, MAXF3);
#pragma unroll
        for (int q = 0; q < 16; q++)
            ((float4*)sW)[t + q * 256] = ((const float4*)W_conv)[t + q * 256];
        if (t < CC) bcs[t] = b_conv[t];
        __syncthreads();

        for (int f = warp; f < nF3; f += 8) {
            int node = g_F3[f];
            int deg = min(g_indeg[node], ADJS);
            float a0 = 0.f, a1 = 0.f, a2 = 0.f, a3 = 0.f;
            for (int j = 0; j < deg; j++) {
                int src = g_adj[node * ADJS + j];
                const float* p = &g_h2[(((unsigned)b << 9) + g_slotF2[src]) * CC];
                a0 += p[lane]; a1 += p[lane + 32]; a2 += p[lane + 64]; a3 += p[lane + 96];
            }
            float* rb = &rowbuf[warp * CC];
            rb[lane] = a0; rb[lane + 32] = a1; rb[lane + 64] = a2; rb[lane + 96] = a3;
            __syncwarp();
            float y0 = 0.f, y1 = 0.f, y2 = 0.f, y3 = 0.f;
#pragma unroll 4
            for (int j = 0; j < CC; j++) {
                float r = rb[j];
                const float* wr = &sW[j * CC];
                y0 += r * wr[lane]; y1 += r * wr[lane + 32];
                y2 += r * wr[lane + 64]; y3 += r * wr[lane + 96];
            }
            h3s[f * CC + lane]      = RELU(y0 + bcs[lane]);
            h3s[f * CC + lane + 32] = RELU(y1 + bcs[lane + 32]);
            h3s[f * CC + lane + 64] = RELU(y2 + bcs[lane + 64]);
            h3s[f * CC + lane + 96] = RELU(y3 + bcs[lane + 96]);
            __syncwarp();
        }
        __syncthreads();

        if (t < CC) {
            int deg0 = min(g_indeg[0], ADJS);
            float a = 0.f;
            for (int j = 0; j < deg0; j++)
                a += h3s[g_slotF3[g_adj[j]] * CC + t];
            agg[t] = a;
        }
        __syncthreads();
        if (t < CC) {
            float y = 0.f;
#pragma unroll 8
            for (int j = 0; j < CC; j++) y += agg[j] * sW[j * CC + t];
            y = RELU(y + bcs[t]);
            float v = y * Wcls[t];
#pragma unroll
            for (int o = 16; o; o >>= 1) v += __shfl_xor_sync(0xffffffffu, v, o);
            if (lane == 0) red[warp] = v;
        }
        __syncthreads();
        if (t == 0) out[b] = red[0] + red[1] + red[2] + red[3] + bcls[0];
    }
}

// ---------------- launch: ONE kernel ----------------
extern "C" void kernel_launch(void* const* d_in, const int* in_sizes, int n_in,
                              void* d_out, int out_size) {
    const float* x      = (const float*)d_in[0];
    const void*  ei     = d_in[1];
    const float* W_emb  = (const float*)d_in[2];
    const float* b_emb  = (const float*)d_in[3];
    const float* W_conv = (const float*)d_in[4];
    const float* b_conv = (const float*)d_in[5];
    const float* W_cls  = (const float*)d_in[6];
    const float* b_cls  = (const float*)d_in[7];
    float* out = (float*)d_out;

    (void)cudaFuncSetAttribute(k_all, cudaFuncAttributeMaxDynamicSharedMemorySize, SMEM_ALL);
    k_all<<<NB, 256, SMEM_ALL>>>(x, ei, W_emb, b_emb, W_conv, b_conv, W_cls, b_cls, out);
}

// round 11
// speedup vs baseline: 1.7351x; 1.1187x over previous
#include <cuda_runtime.h>

#define NB 128     // persistent grid (<=148 SMs, 1 block/SM)
#define NT 512     // threads per block
#define BB 64      // batch
#define NN 1024    // nodes
#define EE 16384   // edges
#define DD 1024    // input dim
#define CC 128     // channels
#define KMAXC 128  // indeg class cap
#define NKPAD 64   // padded class count (actual ~35)
#define ADJS 96    // adjacency stride (max indeg ~40)
#define MAXF2 512  // cap |F2| (actual ~225)
#define MAXF3 64   // cap |F3| (actual ~16)
#define NKC 16     // k-chunks for embedding GEMM
#define RELU(x) fmaxf((x), 0.f)

// ---------------- device scratch ----------------
__device__ int   g_e32;
__device__ int   g_indeg[NN];
__device__ int   g_adj[NN * ADJS];
__device__ int   g_inF3[NN], g_inF2[NN];
__device__ int   g_F3[MAXF3], g_F2[MAXF2];
__device__ int   g_slotF2[NN], g_slotF3[NN];
__device__ int   g_slot2cls[NKPAD];
__device__ int   g_cls2slotG[KMAXC];
__device__ int   g_nF3, g_nF2, g_nk;
__device__ float g_cnt2[MAXF2 * NKPAD];
__device__ float g_Epart[NKC * BB * CC];
__device__ float g_h2[BB * MAXF2 * CC];
__device__ unsigned g_arrive;   // returns to 0 after each barrier
__device__ unsigned g_gen;      // monotonically increasing generation

// ---------------- software grid barrier (all NB blocks co-resident) ----------------
__device__ __forceinline__ void gridbar() {
    __syncthreads();
    __threadfence();
    if (threadIdx.x == 0) {
        unsigned gen = atomicAdd(&g_gen, 0u);
        if (atomicAdd(&g_arrive, 1u) == NB - 1) {
            g_arrive = 0u;
            __threadfence();
            atomicAdd(&g_gen, 1u);
        } else {
            while (atomicAdd(&g_gen, 0u) == gen) { }
        }
    }
    __syncthreads();
}

// smem (floats): max(mid 25216, tail 25864, embed 4096) = 25864
#define SMEM_ALL (25864 * 4)

__global__ void __launch_bounds__(NT, 1)
k_all(const float* __restrict__ x, const void* __restrict__ ei,
      const float* __restrict__ W_emb, const float* __restrict__ b_emb,
      const float* __restrict__ W_conv, const float* __restrict__ b_conv,
      const float* __restrict__ Wcls, const float* __restrict__ bcls,
      float* __restrict__ out) {
    extern __shared__ float S[];
    __shared__ int s_used[KMAXC];
    __shared__ int scls[NKPAD];
    const int blk = blockIdx.x, t = threadIdx.x;
    const int warp = t >> 5, lane = t & 31;

    // ================= phase 0: zero + dtype detect =================
    {
        int gt = blk * NT + t, nth = NB * NT;
        for (int i = gt; i < NN; i += nth) { g_indeg[i] = 0; g_inF3[i] = 0; g_inF2[i] = 0; }
        for (int i = gt; i < MAXF2 * NKPAD; i += nth) g_cnt2[i] = 0.f;
        if (gt == 0) {
            g_nF3 = 0; g_nF2 = 0;
            const long long* p = (const long long*)ei;
            int e32 = 0;
            for (int j = 0; j < 16; j++) { long long v = p[j]; if (v < 0 || v >= (long long)NN) e32 = 1; }
            g_e32 = e32;
        }
    }
    gridbar();

    // ===== phase 1: edges (blocks 0-15) | embed partials (blocks 64-127) =====
    if (blk < 16) {
        int e32 = g_e32;
        const int* pi = (const int*)ei;
        const long long* pl = (const long long*)ei;
        for (int e = blk * NT + t; e < EE; e += 16 * NT) {
            int sv = e32 ? pi[e] : (int)pl[e];
            int dv = e32 ? pi[EE + e] : (int)pl[EE + e];
            int pos = atomicAdd(&g_indeg[dv], 1);
            if (pos < ADJS) g_adj[dv * ADJS + pos] = sv;
            if (dv == 0) {
                if (atomicExch(&g_inF3[sv], 1) == 0) {
                    int sl = atomicAdd(&g_nF3, 1);
                    if (sl < MAXF3) { g_F3[sl] = sv; g_slotF3[sv] = sl; }
                    else g_slotF3[sv] = MAXF3 - 1;
                }
            }
        }
    } else if (blk >= 64) {
        // embed partials: unit -> (strip, kc); W_emb read once chip-wide
        float* xs = S;                       // [64][64]
        int unit = blk - 64;
        int strip = unit >> 4, kc = unit & 15;
        int k0 = kc * 64;
        for (int i = t; i < BB * 16; i += NT) {
            int b = i >> 4, j4 = (i & 15) * 4;
            *(float4*)&xs[b * 64 + j4] = *(const float4*)&x[b * DD + k0 + j4];
        }
        __syncthreads();
        int col = strip * 32 + lane;
        int b0 = warp * 4;                   // 16 warps x 4 rows = 64
        float acc[4] = {};
        for (int k = 0; k < 64; k += 4) {
            float w0 = W_emb[(k0 + k + 0) * CC + col];
            float w1 = W_emb[(k0 + k + 1) * CC + col];
            float w2 = W_emb[(k0 + k + 2) * CC + col];
            float w3 = W_emb[(k0 + k + 3) * CC + col];
#pragma unroll
            for (int r = 0; r < 4; r++) {
                float4 a = *(float4*)&xs[(b0 + r) * 64 + k];
                acc[r] += a.x * w0 + a.y * w1 + a.z * w2 + a.w * w3;
            }
        }
#pragma unroll
        for (int r = 0; r < 4; r++)
            g_Epart[(kc * BB + b0 + r) * CC + col] = acc[r];
    }
    gridbar();

    // ===== phase 2: classes (block 0) | F2 discovery (blocks 1-12) =====
    if (blk == 0) {
        if (t < KMAXC) s_used[t] = 0;
        __syncthreads();
        for (int v = t; v < NN; v += NT)
            s_used[min(g_indeg[v], KMAXC - 1)] = 1;
        __syncthreads();
        if (t == 0) {
            int nk = 0;
            for (int k = 0; k < KMAXC; k++) {
                if (s_used[k]) {
                    g_cls2slotG[k] = (nk < NKPAD) ? nk : NKPAD - 1;
                    if (nk < NKPAD) g_slot2cls[nk] = k;
                    nk++;
                } else g_cls2slotG[k] = 0;
            }
            g_nk = min(nk, NKPAD);
        }
    } else if (blk <= 12) {
        int idx = (blk - 1) * NT + t;        // over MAXF3 * ADJS = 6144
        int f = idx / ADJS, j = idx % ADJS;
        int nf3 = min(g_nF3, MAXF3);
        if (f < nf3) {
            int w = g_F3[f];
            if (j < min(g_indeg[w], ADJS)) {
                int src = g_adj[w * ADJS + j];
                if (atomicExch(&g_inF2[src], 1) == 0) {
                    int sl = atomicAdd(&g_nF2, 1);
                    if (sl < MAXF2) { g_F2[sl] = src; g_slotF2[src] = sl; }
                    else g_slotF2[src] = MAXF2 - 1;
                }
            }
        }
    }
    gridbar();

    // ===== phase 3: class-count matrix (one item per thread) =====
    {
        int nf2 = min(g_nF2, MAXF2);
        int idx = blk * NT + t;              // NB*NT = 65536 >= MAXF2*ADJS = 49152
        if (idx < MAXF2 * ADJS) {
            int sl = idx / ADJS, j = idx % ADJS;
            if (sl < nf2) {
                int u = g_F2[sl];
                if (j < min(g_indeg[u], ADJS)) {
                    int src = g_adj[u * ADJS + j];
                    int cs = g_cls2slotG[min(g_indeg[src], KMAXC - 1)];
                    atomicAdd(&g_cnt2[sl * NKPAD + cs], 1.f);
                }
            }
        }
    }
    gridbar();

    // ===== phase 4: mid (b = blk>>1, col-half = blk&1) =====
    {
        float* sWh  = S;           // [128][64]
        float* sA1  = S + 8192;    // [64][128]
        float* sH1  = S + 16384;   // [64][64]
        float* sCnt = S + 20480;   // [64][64]
        float* e_s  = S + 24576;
        float* hw0f = S + 24704;
        float* part = S + 24832;   // 256 floats
        float* bcs  = S + 25088;
        int b = blk >> 1, n0 = (blk & 1) * 64;
        int nk = g_nk, nF2 = min(g_nF2, MAXF2);
        int nk4 = (nk + 3) & ~3;

        if (t < CC) {
            float s = b_emb[t];
#pragma unroll
            for (int kc = 0; kc < NKC; kc++) s += g_Epart[(kc * BB + b) * CC + t];
            e_s[t] = RELU(s);
            bcs[t] = b_conv[t];
        }
        if (t < NKPAD) scls[t] = g_slot2cls[t];
#pragma unroll
        for (int q = 0; q < 4; q++) {        // W half: 2048 float4
            int idx = t + q * NT;
            int row = idx >> 4, c4 = (idx & 15) * 4;
            *(float4*)&sWh[row * 64 + c4] = *(const float4*)&W_conv[row * CC + n0 + c4];
        }
        __syncthreads();

        {   // hw0 full, K split over 2 groups of 256 threads (threads 0-511 -> 2x (c,kh))
            int c = t & 127, kh = (t >> 7) & 1;    // t in [0,256): kh 0/1... use t>>7 in 0..3
            int g2 = t >> 7;                        // 0..3: (c, khalf) pairs: g2&1 = khalf over 64
            float a = 0.f;
            int j0 = (g2 & 1) * 64 + (g2 >> 1) * 32;  // quarters of K=128: 0,64 / 32,96
            // simpler: 4 groups each 32 K values
            a = 0.f;
#pragma unroll 8
            for (int j = g2 * 32; j < g2 * 32 + 32; j++)
                a += e_s[j] * W_conv[j * CC + c];
            (void)kh; (void)j0;
            part[0]; // keep part base alive
            // store partials: part has 256 floats -> need 512; reuse sA1 head instead
            sA1[g2 * CC + c] = a;
        }
        __syncthreads();
        if (t < CC) hw0f[t] = sA1[t] + sA1[CC + t] + sA1[2 * CC + t] + sA1[3 * CC + t];
        __syncthreads();

        // A1[slot][k] = relu(cls*hw0[k] + b) (rows >= nk zero)
        for (int idx = t; idx < NKPAD * CC; idx += NT) {
            int slot = idx >> 7, k = idx & 127;
            float v = 0.f;
            if (slot < nk) v = RELU((float)scls[slot] * hw0f[k] + bcs[k]);
            sA1[idx] = v;
        }
        __syncthreads();

        {   // hw1c half: 16 warps x 4 rows, K=128
            int rb = warp * 4, cb = lane * 2;
            if (rb < nk) {
                float acc[4][2] = {};
                for (int k = 0; k < CC; k += 4) {
                    float2 wv0 = *(float2*)&sWh[(k + 0) * 64 + cb];
                    float2 wv1 = *(float2*)&sWh[(k + 1) * 64 + cb];
                    float2 wv2 = *(float2*)&sWh[(k + 2) * 64 + cb];
                    float2 wv3 = *(float2*)&sWh[(k + 3) * 64 + cb];
#pragma unroll
                    for (int r = 0; r < 4; r++) {
                        float4 a = *(float4*)&sA1[(rb + r) * CC + k];
                        acc[r][0] += a.x * wv0.x + a.y * wv1.x + a.z * wv2.x + a.w * wv3.x;
                        acc[r][1] += a.x * wv0.y + a.y * wv1.y + a.z * wv2.y + a.w * wv3.y;
                    }
                }
#pragma unroll
                for (int r = 0; r < 4; r++)
                    *(float2*)&sH1[(rb + r) * 64 + cb] = make_float2(acc[r][0], acc[r][1]);
            } else if (rb < NKPAD) {
#pragma unroll
                for (int r = 0; r < 4; r++)
                    *(float2*)&sH1[(rb + r) * 64 + cb] = make_float2(0.f, 0.f);
            }
        }
        __syncthreads();

        {   // h2 half: chunks of 64 rows, 16 warps x 4 rows, K=nk4
            int rb = warp * 4, cb = lane * 2;
            float2 bc2 = *(float2*)&bcs[n0 + cb];
            for (int r0 = 0; r0 < nF2; r0 += 64) {
#pragma unroll
                for (int q = 0; q < 2; q++)
                    ((float4*)sCnt)[t + q * NT] = ((const float4*)&g_cnt2[r0 * NKPAD])[t + q * NT];
                __syncthreads();
                float acc[4][2] = {};
                for (int k = 0; k < nk4; k += 4) {
                    float2 wv0 = *(float2*)&sH1[(k + 0) * 64 + cb];
                    float2 wv1 = *(float2*)&sH1[(k + 1) * 64 + cb];
                    float2 wv2 = *(float2*)&sH1[(k + 2) * 64 + cb];
                    float2 wv3 = *(float2*)&sH1[(k + 3) * 64 + cb];
#pragma unroll
                    for (int r = 0; r < 4; r++) {
                        float4 a = *(float4*)&sCnt[(rb + r) * NKPAD + k];
                        acc[r][0] += a.x * wv0.x + a.y * wv1.x + a.z * wv2.x + a.w * wv3.x;
                        acc[r][1] += a.x * wv0.y + a.y * wv1.y + a.z * wv2.y + a.w * wv3.y;
                    }
                }
#pragma unroll
                for (int r = 0; r < 4; r++) {
                    int row = r0 + rb + r;
                    if (row < nF2)
                        *(float2*)&g_h2[(((unsigned)b << 9) + row) * CC + n0 + cb] =
                            make_float2(RELU(acc[r][0] + bc2.x), RELU(acc[r][1] + bc2.y));
                }
                __syncthreads();
            }
        }
    }
    gridbar();

    // ===== phase 5: tail (blocks 0-63) =====
    if (blk < BB) {
        float* sW     = S;            // [128][128]
        float* h3s    = S + 16384;    // [64][128]
        float* rowbuf = S + 24576;    // [16][...] -> use 16x64? need 16 warps x 128 = 2048 > 1024
        float* agg    = S + 25600;
        float* red    = S + 25728;    // 16
        float* bcs    = S + 25744;
        int b = blk;
        int nF3 = min(g_nF3, MAXF3);
#pragma unroll
        for (int q = 0; q < 8; q++)
            ((float4*)sW)[t + q * NT] = ((const float4*)W_conv)[t + q * NT];
        if (t < CC) bcs[t] = b_conv[t];
        __syncthreads();

        // one warp per F3 node (single pass for nF3<=16); rowbuf shared via h3s staging:
        // stage agg-row into h3s[f] first, then overwrite with h3 output.
        for (int f = warp; f < nF3; f += 16) {
            int node = g_F3[f];
            int deg = min(g_indeg[node], ADJS);
            float a0 = 0.f, a1 = 0.f, a2 = 0.f, a3 = 0.f;
            for (int j = 0; j < deg; j++) {
                int src = g_adj[node * ADJS + j];
                const float* p = &g_h2[(((unsigned)b << 9) + g_slotF2[src]) * CC];
                a0 += p[lane]; a1 += p[lane + 32]; a2 += p[lane + 64]; a3 += p[lane + 96];
            }
            float* rb = &h3s[f * CC];
            rb[lane] = a0; rb[lane + 32] = a1; rb[lane + 64] = a2; rb[lane + 96] = a3;
            __syncwarp();
            float y0 = 0.f, y1 = 0.f, y2 = 0.f, y3 = 0.f;
#pragma unroll 4
            for (int j = 0; j < CC; j++) {
                float r = rb[j];
                const float* wr = &sW[j * CC];
                y0 += r * wr[lane]; y1 += r * wr[lane + 32];
                y2 += r * wr[lane + 64]; y3 += r * wr[lane + 96];
            }
            __syncwarp();
            rb[lane]      = RELU(y0 + bcs[lane]);
            rb[lane + 32] = RELU(y1 + bcs[lane + 32]);
            rb[lane + 64] = RELU(y2 + bcs[lane + 64]);
            rb[lane + 96] = RELU(y3 + bcs[lane + 96]);
            __syncwarp();
        }
        __syncthreads();

        if (t < CC) {
            int deg0 = min(g_indeg[0], ADJS);
            float a = 0.f;
            for (int j = 0; j < deg0; j++)
                a += h3s[g_slotF3[g_adj[j]] * CC + t];
            agg[t] = a;
        }
        __syncthreads();
        if (t < CC) {
            float y = 0.f;
#pragma unroll 8
            for (int j = 0; j < CC; j++) y += agg[j] * sW[j * CC + t];
            y = RELU(y + bcs[t]);
            float v = y * Wcls[t];
#pragma unroll
            for (int o = 16; o; o >>= 1) v += __shfl_xor_sync(0xffffffffu, v, o);
            if (lane == 0) red[warp] = v;
        }
        __syncthreads();
        if (t == 0) out[b] = red[0] + red[1] + red[2] + red[3] + bcls[0];
    }
}

// ---------------- launch: ONE kernel ----------------
extern "C" void kernel_launch(void* const* d_in, const int* in_sizes, int n_in,
                              void* d_out, int out_size) {
    const float* x      = (const float*)d_in[0];
    const void*  ei     = d_in[1];
    const float* W_emb  = (const float*)d_in[2];
    const float* b_emb  = (const float*)d_in[3];
    const float* W_conv = (const float*)d_in[4];
    const float* b_conv = (const float*)d_in[5];
    const float* W_cls  = (const float*)d_in[6];
    const float* b_cls  = (const float*)d_in[7];
    float* out = (float*)d_out;

    (void)cudaFuncSetAttribute(k_all, cudaFuncAttributeMaxDynamicSharedMemorySize, SMEM_ALL);
    k_all<<<NB, NT, SMEM_ALL>>>(x, ei, W_emb, b_emb, W_conv, b_conv, W_cls, b_cls, out);
}